// round 2
// baseline (speedup 1.0000x reference)
#include <cuda_runtime.h>
#include <cstdint>

typedef unsigned long long ull;

#define B_TOT 1024
#define T_LEN 512
#define NU    64
#define NB    8
#define NCTA  128
#define THR   256
#define APITCH 20   // floats per A row (16 used + pad); 80B keeps 16B alignment

// Layer activation ping-pong buffer: h[b][t][u], 128 MiB.
__device__ float g_h[(size_t)B_TOT * T_LEN * NU];

__device__ __forceinline__ ull ffma2(ull a, ull b, ull c) {
    ull d;
    asm("fma.rn.f32x2 %0, %1, %2, %3;" : "=l"(d) : "l"(a), "l"(b), "l"(c));
    return d;
}
__device__ __forceinline__ float sigf(float x) {
    return __fdividef(1.0f, 1.0f + __expf(-x));
}

// KX = input feature rows (1 for layer0, 64 otherwise). KTOT = KX + 64.
// LAST: only write g_h at t == T_LEN-1.
template <int KX, bool LAST>
__global__ void __launch_bounds__(THR, 1)
lstm_layer(const float* __restrict__ xin, const float* __restrict__ Wx,
           const float* __restrict__ U,   const float* __restrict__ bias)
{
    constexpr int KTOT = KX + NU;
    extern __shared__ float sm[];
    float* Wsh = sm;                      // [KTOT][256]
    float* Ash = Wsh + KTOT * 256;        // [KTOT][APITCH], dup pairs (a,a) x 8 rows
    float* Zsh = Ash + KTOT * APITCH;     // [8][256]

    const int tid = threadIdx.x;
    const int j2  = tid & 127;            // column pair: cols 2*j2, 2*j2+1
    const int rh  = tid >> 7;             // row half: batch rows 4*rh..4*rh+3
    const int bg0 = blockIdx.x * NB;      // global batch base for this CTA

    // ---- stage weights: rows 0..KX-1 = Wx, rows KX..KTOT-1 = U ----
    for (int i = tid; i < KTOT * 256; i += THR) {
        int r = i >> 8, c = i & 255;
        Wsh[i] = (r < KX) ? Wx[i] : U[(r - KX) * 256 + c];
    }
    // zero h rows of A (h0 = 0)
    for (int i = tid; i < NU * APITCH; i += THR) Ash[KX * APITCH + i] = 0.0f;

    const ull bpair = *(const ull*)(bias + 2 * j2);

    // per-thread epilogue state: cells tid and tid+256 -> (b = cell>>6, u = cell&63)
    float cs0 = 0.0f, cs1 = 0.0f;
    const int eb0 = tid >> 6, eu = tid & 63;       // cell 0: (eb0, eu)
    const int eb1 = eb0 + 4;                       // cell 1: (eb1, eu)

    // ---- initial prefetch (t = 0) ----
    float xv = 0.0f, v0 = 0.0f, v1 = 0.0f;
    if (KX == 1) {
        if (tid < NB) xv = xin[(size_t)(bg0 + tid) * T_LEN + 0];
    } else {
        v0 = g_h[((size_t)(bg0 + eb0) * T_LEN + 0) * NU + eu];
        v1 = g_h[((size_t)(bg0 + eb1) * T_LEN + 0) * NU + eu];
    }

    for (int t = 0; t < T_LEN; ++t) {
        // (1) stage input rows of A from prefetch regs (duplicated pairs)
        if (KX == 1) {
            if (tid < NB) { Ash[2 * tid] = xv; Ash[2 * tid + 1] = xv; }
        } else {
            float* p0 = Ash + eu * APITCH + 2 * eb0;
            p0[0] = v0; p0[1] = v0;
            float* p1 = Ash + eu * APITCH + 2 * eb1;
            p1[0] = v1; p1[1] = v1;
        }
        __syncthreads();   // B1: A complete (h rows from prev epilogue, x rows now)

        // (3) prefetch next step's input (hidden under matmul)
        const int tn = (t + 1 < T_LEN) ? t + 1 : T_LEN - 1;
        if (KX == 1) {
            if (tid < NB) xv = xin[(size_t)(bg0 + tid) * T_LEN + tn];
        } else {
            v0 = g_h[((size_t)(bg0 + eb0) * T_LEN + tn) * NU + eu];
            v1 = g_h[((size_t)(bg0 + eb1) * T_LEN + tn) * NU + eu];
        }

        // (4) matmul: acc[i] = bias + sum_k A[k][row] * W[k][colpair]
        ull a0 = bpair, a1 = bpair, a2 = bpair, a3 = bpair;
        const float* wp = Wsh + 2 * j2;
        const float* ap = Ash + 8 * rh;
        #pragma unroll 16
        for (int k = 0; k < KTOT; ++k) {
            ull w = *(const ull*)(wp + (size_t)k * 256);
            ulonglong2 pA = *(const ulonglong2*)(ap + k * APITCH);
            ulonglong2 pB = *(const ulonglong2*)(ap + k * APITCH + 4);
            a0 = ffma2(pA.x, w, a0);
            a1 = ffma2(pA.y, w, a1);
            a2 = ffma2(pB.x, w, a2);
            a3 = ffma2(pB.y, w, a3);
        }

        // (5) scatter z to shared
        {
            float* zb = Zsh + (4 * rh) * 256 + 2 * j2;
            *(ull*)(zb + 0 * 256) = a0;
            *(ull*)(zb + 1 * 256) = a1;
            *(ull*)(zb + 2 * 256) = a2;
            *(ull*)(zb + 3 * 256) = a3;
        }
        __syncthreads();   // B2: Z complete; all A reads done

        // (7) epilogue: 2 cells per thread
        #pragma unroll
        for (int cc = 0; cc < 2; ++cc) {
            const int b = cc ? eb1 : eb0;
            const float* zr = Zsh + b * 256 + eu;
            float zi = zr[0], zf = zr[64], zg = zr[128], zo = zr[192];
            float ii = sigf(zi), ff = sigf(zf), oo = sigf(zo);
            float gg = fmaxf(zg, 0.0f);
            float c_new = ff * (cc ? cs1 : cs0) + ii * gg;
            if (cc) cs1 = c_new; else cs0 = c_new;
            float h = oo * fmaxf(c_new, 0.0f);
            float* hp = Ash + (KX + eu) * APITCH + 2 * b;
            hp[0] = h; hp[1] = h;
            if (!LAST || t == T_LEN - 1)
                g_h[((size_t)(bg0 + b) * T_LEN + t) * NU + eu] = h;
        }
        // next iter's B1 orders epilogue writes before matmul reads
    }
}

__global__ void __launch_bounds__(256)
head_kernel(const float* __restrict__ Wd, const float* __restrict__ bd,
            float* __restrict__ out)
{
    __shared__ float wd[NU];
    if (threadIdx.x < NU) wd[threadIdx.x] = Wd[threadIdx.x];
    __syncthreads();
    int b = blockIdx.x * blockDim.x + threadIdx.x;
    const float* hp = g_h + ((size_t)b * T_LEN + (T_LEN - 1)) * NU;
    float s = 0.0f;
    #pragma unroll
    for (int u = 0; u < NU; ++u) s += hp[u] * wd[u];
    out[b] = s + bd[0];
}

extern "C" void kernel_launch(void* const* d_in, const int* in_sizes, int n_in,
                              void* d_out, int out_size)
{
    const float* x   = (const float*)d_in[0];
    const float* Wx0 = (const float*)d_in[1];
    const float* U0  = (const float*)d_in[2];
    const float* b0  = (const float*)d_in[3];
    const float* Wx1 = (const float*)d_in[4];
    const float* U1  = (const float*)d_in[5];
    const float* b1  = (const float*)d_in[6];
    const float* Wx2 = (const float*)d_in[7];
    const float* U2  = (const float*)d_in[8];
    const float* b2  = (const float*)d_in[9];
    const float* Wx3 = (const float*)d_in[10];
    const float* U3  = (const float*)d_in[11];
    const float* b3  = (const float*)d_in[12];
    const float* Wd  = (const float*)d_in[13];
    const float* bd  = (const float*)d_in[14];
    float* out = (float*)d_out;

    const int KT0 = 1 + NU, KT1 = 64 + NU;
    const size_t smem0 = (size_t)(KT0 * 256 + KT0 * APITCH + 8 * 256) * 4;
    const size_t smem1 = (size_t)(KT1 * 256 + KT1 * APITCH + 8 * 256) * 4;

    cudaFuncSetAttribute((const void*)lstm_layer<1, false>,
                         cudaFuncAttributeMaxDynamicSharedMemorySize, (int)smem0);
    cudaFuncSetAttribute((const void*)lstm_layer<64, false>,
                         cudaFuncAttributeMaxDynamicSharedMemorySize, (int)smem1);
    cudaFuncSetAttribute((const void*)lstm_layer<64, true>,
                         cudaFuncAttributeMaxDynamicSharedMemorySize, (int)smem1);

    lstm_layer<1,  false><<<NCTA, THR, smem0>>>(x,       Wx0, U0, b0);
    lstm_layer<64, false><<<NCTA, THR, smem1>>>(nullptr, Wx1, U1, b1);
    lstm_layer<64, false><<<NCTA, THR, smem1>>>(nullptr, Wx2, U2, b2);
    lstm_layer<64, true ><<<NCTA, THR, smem1>>>(nullptr, Wx3, U3, b3);
    head_kernel<<<B_TOT / 256, 256>>>(Wd, bd, out);
}